// round 12
// baseline (speedup 1.0000x reference)
#include <cuda_runtime.h>
#include <cuda_fp16.h>
#include <cstdint>

// ---------------- problem constants ----------------
#define HDIM   256
#define WDIM   256
#define HW     16384          // 128*128 output pixels
#define KB     1024           // K (channels)
#define COUT   512
#define NGROUP 128
#define GSIZE  8
#define GN_EPS 1e-5f
#define TITER  16             // 1024 / 64

// ---------------- device scratch ----------------
__device__ __half g_B[(size_t)KB * HW];        // 32 MB: Y fp16, [k][n]
__device__ __half g_A[(size_t)COUT * KB];      // 1 MB: folded W fp16, [o][k]
__device__ float g_psum[4 * KB];               // per-chunk partial sums
__device__ float g_psumsq[4 * KB];
__device__ float g_biaso[COUT];

// ---------------- PTX helpers (target-generic only) ----------------
__device__ __forceinline__ uint32_t s2u(const void* p) {
    uint32_t a;
    asm("{ .reg .u64 t; cvta.to.shared.u64 t, %1; cvt.u32.u64 %0, t; }" : "=r"(a) : "l"(p));
    return a;
}
__device__ __forceinline__ void cp16(uint32_t dst, const void* src) {
    asm volatile("cp.async.cg.shared.global [%0], [%1], 16;" :: "r"(dst), "l"(src));
}
__device__ __forceinline__ void cp_commit() {
    asm volatile("cp.async.commit_group;" ::: "memory");
}
__device__ __forceinline__ void cp_wait1() {
    asm volatile("cp.async.wait_group 1;" ::: "memory");
}
__device__ __forceinline__ void ldsm4(uint32_t* r, uint32_t a) {
    asm volatile("ldmatrix.sync.aligned.m8n8.x4.shared.b16 {%0,%1,%2,%3}, [%4];"
                 : "=r"(r[0]), "=r"(r[1]), "=r"(r[2]), "=r"(r[3]) : "r"(a));
}
__device__ __forceinline__ void ldsm4t(uint32_t* r, uint32_t a) {
    asm volatile("ldmatrix.sync.aligned.m8n8.x4.trans.shared.b16 {%0,%1,%2,%3}, [%4];"
                 : "=r"(r[0]), "=r"(r[1]), "=r"(r[2]), "=r"(r[3]) : "r"(a));
}
__device__ __forceinline__ void mma16816(float* d, const uint32_t* a, uint32_t b0, uint32_t b1) {
    asm volatile(
        "mma.sync.aligned.m16n8k16.row.col.f32.f16.f16.f32 "
        "{%0,%1,%2,%3}, {%4,%5,%6,%7}, {%8,%9}, {%0,%1,%2,%3};"
        : "+f"(d[0]), "+f"(d[1]), "+f"(d[2]), "+f"(d[3])
        : "r"(a[0]), "r"(a[1]), "r"(a[2]), "r"(a[3]), "r"(b0), "r"(b1));
}

// ---------------- Kernel A: Haar bands -> fp16 + partial stats ----------------
// grid (256 channels, 4 chunks); block: 4096 pixels, split into 2 halves
// processed together per iteration (MLP=4 independent loads).
__global__ __launch_bounds__(256) void haar_kernel(const float* __restrict__ x) {
    const int cx    = blockIdx.x;            // input channel 0..255
    const int chunk = blockIdx.y;            // 0..3
    const float* xp = x + (size_t)cx * (HDIM * WDIM);

    float s0=0.f,s1=0.f,s2=0.f,s3=0.f,q0=0.f,q1=0.f,q2=0.f,q3=0.f;

    const int base = chunk * 4096;
    for (int t = threadIdx.x * 2; t < 2048; t += 512) {
        const int iA = base + t;             // half A of chunk
        const int iB = iA + 2048;            // half B of chunk
        const int hA = iA >> 7, wA = iA & 127;
        const int hB = iB >> 7, wB = iB & 127;
        // 4 independent loads up front
        const float4 a0 = *(const float4*)(xp + (size_t)(2*hA)   * WDIM + 2*wA);
        const float4 a1 = *(const float4*)(xp + (size_t)(2*hA+1) * WDIM + 2*wA);
        const float4 b0 = *(const float4*)(xp + (size_t)(2*hB)   * WDIM + 2*wB);
        const float4 b1 = *(const float4*)(xp + (size_t)(2*hB+1) * WDIM + 2*wB);

        float vA0[4], vA1[4], vB0[4], vB1[4];
        vA0[0] = 0.5f*( a0.x + a0.y + a1.x + a1.y);
        vA0[1] = 0.5f*(-a0.x - a0.y + a1.x + a1.y);
        vA0[2] = 0.5f*(-a0.x + a0.y - a1.x + a1.y);
        vA0[3] = 0.5f*( a0.x - a0.y - a1.x + a1.y);
        vA1[0] = 0.5f*( a0.z + a0.w + a1.z + a1.w);
        vA1[1] = 0.5f*(-a0.z - a0.w + a1.z + a1.w);
        vA1[2] = 0.5f*(-a0.z + a0.w - a1.z + a1.w);
        vA1[3] = 0.5f*( a0.z - a0.w - a1.z + a1.w);
        vB0[0] = 0.5f*( b0.x + b0.y + b1.x + b1.y);
        vB0[1] = 0.5f*(-b0.x - b0.y + b1.x + b1.y);
        vB0[2] = 0.5f*(-b0.x + b0.y - b1.x + b1.y);
        vB0[3] = 0.5f*( b0.x - b0.y - b1.x + b1.y);
        vB1[0] = 0.5f*( b0.z + b0.w + b1.z + b1.w);
        vB1[1] = 0.5f*(-b0.z - b0.w + b1.z + b1.w);
        vB1[2] = 0.5f*(-b0.z + b0.w - b1.z + b1.w);
        vB1[3] = 0.5f*( b0.z - b0.w - b1.z + b1.w);

        #pragma unroll
        for (int b = 0; b < 4; b++) {
            const size_t c = (size_t)b * 256 + cx;
            *(__half2*)&g_B[c * HW + iA] =
                __halves2half2(__float2half_rn(vA0[b]), __float2half_rn(vA1[b]));
            *(__half2*)&g_B[c * HW + iB] =
                __halves2half2(__float2half_rn(vB0[b]), __float2half_rn(vB1[b]));
        }
        s0 += vA0[0]+vA1[0]+vB0[0]+vB1[0];
        q0 += vA0[0]*vA0[0]+vA1[0]*vA1[0]+vB0[0]*vB0[0]+vB1[0]*vB1[0];
        s1 += vA0[1]+vA1[1]+vB0[1]+vB1[1];
        q1 += vA0[1]*vA0[1]+vA1[1]*vA1[1]+vB0[1]*vB0[1]+vB1[1]*vB1[1];
        s2 += vA0[2]+vA1[2]+vB0[2]+vB1[2];
        q2 += vA0[2]*vA0[2]+vA1[2]*vA1[2]+vB0[2]*vB0[2]+vB1[2]*vB1[2];
        s3 += vA0[3]+vA1[3]+vB0[3]+vB1[3];
        q3 += vA0[3]*vA0[3]+vA1[3]*vA1[3]+vB0[3]*vB0[3]+vB1[3]*vB1[3];
    }

    // warp shuffle reduce 8 values, then one smem stage
    float vals[8] = {s0,s1,s2,s3,q0,q1,q2,q3};
    #pragma unroll
    for (int q = 0; q < 8; q++) {
        #pragma unroll
        for (int off = 16; off > 0; off >>= 1)
            vals[q] += __shfl_xor_sync(0xFFFFFFFFu, vals[q], off);
    }
    __shared__ float wred[8][8];             // [warp][metric]
    const int wid = threadIdx.x >> 5;
    const int lid = threadIdx.x & 31;
    if (lid == 0) {
        #pragma unroll
        for (int q = 0; q < 8; q++) wred[wid][q] = vals[q];
    }
    __syncthreads();
    if (threadIdx.x < 8) {
        const int q = threadIdx.x;
        float r = 0.f;
        #pragma unroll
        for (int w = 0; w < 8; w++) r += wred[w][q];
        const int band = q & 3;
        const int idx = chunk * KB + band * 256 + cx;
        if (q < 4) g_psum[idx]   = r;
        else       g_psumsq[idx] = r;
    }
}

// ---------------- Kernel B: stats + fold affine into fp16 weights ------
__global__ __launch_bounds__(256) void foldw_kernel(const float* __restrict__ w,
                                                    const float* __restrict__ scale,
                                                    const float* __restrict__ bias) {
    __shared__ float sa[KB], sb[KB];
    const int tid = threadIdx.x;
    if (tid < NGROUP) {
        const int g = tid;
        float s = 0.f, q = 0.f;
        #pragma unroll
        for (int j = 0; j < GSIZE; j++) {
            const int c = g*GSIZE + j;
            #pragma unroll
            for (int ch = 0; ch < 4; ch++) {
                s += g_psum[ch * KB + c];
                q += g_psumsq[ch * KB + c];
            }
        }
        const float inv  = 1.0f / (float)(GSIZE * HW);
        const float mean = s * inv;
        const float var  = q * inv - mean * mean;
        const float rstd = rsqrtf(var + GN_EPS);
        #pragma unroll
        for (int j = 0; j < GSIZE; j++) {
            const int c = g*GSIZE + j;
            const float a = scale[c] * rstd;
            sa[c] = a;
            sb[c] = bias[c] - mean * a;
        }
    }
    __syncthreads();

    const int o = blockIdx.x;                // 0..511
    float part = 0.f;
    for (int c = tid; c < KB; c += 256) {
        const float wv = w[(size_t)o * KB + c];
        g_A[(size_t)o * KB + c] = __float2half_rn(wv * sa[c]);
        part += wv * sb[c];
    }
    __shared__ float red[256];
    red[tid] = part;
    __syncthreads();
    for (int off = 128; off > 0; off >>= 1) {
        if (tid < off) red[tid] += red[tid + off];
        __syncthreads();
    }
    if (tid == 0) g_biaso[o] = red[0];
}

// ---------------- Kernel C: mma.sync fp16 GEMM + bias + ReLU (R9-best) ----
// CTA tile 128(M) x 64(N), BK=64; 8 warps, warp tile 32x32 (4x2 warp grid).
// Stage: A 16KB + B 8KB = 24KB; 3 stages = 72KB. 3 CTAs/SM (24 warps).
#define STAGE_BYTES 24576
#define GEMM_SMEM   (3 * STAGE_BYTES)

__device__ __forceinline__ void load_stage(int tid, int j, uint32_t sbase, int m0, int n0) {
    const uint32_t st = sbase + (uint32_t)(j % 3) * STAGE_BYTES;
    const int koff = j << 6;                 // 0..960
    const __half* Ab = g_A + (size_t)m0 * KB + koff;
    const __half* Bb = g_B + (size_t)koff * HW + n0;
    // A: 128 rows(m) x 8 chunks(kc of 8 halves); unit = m*8 + (kc ^ (m&7))
    #pragma unroll
    for (int t = 0; t < 4; t++) {
        const int u = tid + t * 256;
        const int m = u >> 3, kc = u & 7;
        const uint32_t du = (uint32_t)(m * 8 + (kc ^ (m & 7))) * 16;
        cp16(st + du, Ab + (size_t)m * KB + kc * 8);
    }
    // B: 64 rows(k) x 8 chunks(nc of 8 halves); unit = k*8 + (nc ^ (k&7))
    #pragma unroll
    for (int t = 0; t < 2; t++) {
        const int u = tid + t * 256;
        const int k = u >> 3, nc = u & 7;
        const uint32_t du = (uint32_t)(k * 8 + (nc ^ (k & 7)));
        cp16(st + 16384 + du * 16, Bb + (size_t)k * HW + nc * 8);
    }
}

__global__ __launch_bounds__(256, 3) void gemm_mma_kernel(float* __restrict__ out) {
    extern __shared__ char smem[];
    const uint32_t sbase = s2u(smem);
    const int tid  = threadIdx.x;
    const int wid  = tid >> 5;
    const int lane = tid & 31;
    const int n0 = blockIdx.x * 64;
    const int m0 = blockIdx.y * 128;
    const int wm = wid >> 1;                 // 0..3
    const int wn = wid & 1;                  // 0..1
    const int mbase = wm * 32;
    const int nbase = wn * 32;

    const int r15 = lane & 15;
    const int hi  = lane >> 4;
    const int s7  = r15 & 7;

    float acc[2][4][4];
    #pragma unroll
    for (int i = 0; i < 2; i++)
        #pragma unroll
        for (int j = 0; j < 4; j++)
            #pragma unroll
            for (int q = 0; q < 4; q++) acc[i][j][q] = 0.f;

    load_stage(tid, 0, sbase, m0, n0); cp_commit();
    load_stage(tid, 1, sbase, m0, n0); cp_commit();

    for (int j = 0; j < TITER; j++) {
        cp_wait1();
        __syncthreads();
        if (j + 2 < TITER) load_stage(tid, j + 2, sbase, m0, n0);
        cp_commit();

        const uint32_t st = sbase + (uint32_t)(j % 3) * STAGE_BYTES;
        #pragma unroll
        for (int kk = 0; kk < 4; kk++) {
            uint32_t b[2][4];
            #pragma unroll
            for (int p = 0; p < 2; p++) {
                const int k   = kk * 16 + r15;
                const int ncg = wn * 4 + p * 2 + hi;
                ldsm4t(b[p], st + 16384 + (uint32_t)((k * 8 + (ncg ^ s7)) * 16));
            }
            uint32_t a[2][4];
            #pragma unroll
            for (int mf = 0; mf < 2; mf++) {
                const int row = mbase + mf * 16 + r15;
                ldsm4(a[mf], st + (uint32_t)(row * 128) + (uint32_t)(((kk * 2 + hi) ^ s7) * 16));
            }
            #pragma unroll
            for (int mf = 0; mf < 2; mf++)
                #pragma unroll
                for (int nf = 0; nf < 4; nf++)
                    mma16816(acc[mf][nf], a[mf], b[nf >> 1][(nf & 1) * 2],
                             b[nf >> 1][(nf & 1) * 2 + 1]);
        }
    }

    // epilogue: bias + ReLU + float2 stores
    const int qrow = lane >> 2;
    const int qcol = (lane & 3) * 2;
    #pragma unroll
    for (int mf = 0; mf < 2; mf++) {
        const int row0 = m0 + mbase + mf * 16 + qrow;
        const float bi0 = g_biaso[row0];
        const float bi1 = g_biaso[row0 + 8];
        float* o0 = out + (size_t)row0 * HW + n0 + nbase + qcol;
        float* o1 = out + (size_t)(row0 + 8) * HW + n0 + nbase + qcol;
        #pragma unroll
        for (int nf = 0; nf < 4; nf++) {
            float2 v0, v1;
            v0.x = fmaxf(acc[mf][nf][0] + bi0, 0.f);
            v0.y = fmaxf(acc[mf][nf][1] + bi0, 0.f);
            v1.x = fmaxf(acc[mf][nf][2] + bi1, 0.f);
            v1.y = fmaxf(acc[mf][nf][3] + bi1, 0.f);
            *(float2*)(o0 + nf * 8) = v0;
            *(float2*)(o1 + nf * 8) = v1;
        }
    }
}

// ---------------- launch ----------------
extern "C" void kernel_launch(void* const* d_in, const int* in_sizes, int n_in,
                              void* d_out, int out_size) {
    const float* x        = (const float*)d_in[0];
    const float* gn_scale = (const float*)d_in[1];
    const float* gn_bias  = (const float*)d_in[2];
    const float* w_proj   = (const float*)d_in[3];
    float* out = (float*)d_out;

    cudaFuncSetAttribute(gemm_mma_kernel,
                         cudaFuncAttributeMaxDynamicSharedMemorySize, GEMM_SMEM);

    dim3 hgrid(256, 4);
    haar_kernel<<<hgrid, 256>>>(x);
    foldw_kernel<<<COUT, 256>>>(w_proj, gn_scale, gn_bias);
    dim3 grid(HW / 64, COUT / 128);
    gemm_mma_kernel<<<grid, 256, GEMM_SMEM>>>(out);
}

// round 13
// speedup vs baseline: 1.0370x; 1.0370x over previous
#include <cuda_runtime.h>
#include <cuda_fp16.h>
#include <cstdint>

// ---------------- problem constants ----------------
#define HDIM   256
#define WDIM   256
#define HW     16384          // 128*128 output pixels
#define KB     1024           // K (channels)
#define COUT   512
#define NGROUP 128
#define GSIZE  8
#define GN_EPS 1e-5f
#define TITER  16             // 1024 / 64

// ---------------- device scratch ----------------
__device__ __half g_B[(size_t)KB * HW];        // 32 MB: Y fp16, [k][n]
__device__ __half g_A[(size_t)COUT * KB];      // 1 MB: folded W fp16, [o][k]
__device__ float g_psum[2 * KB];               // per-chunk partial sums
__device__ float g_psumsq[2 * KB];
__device__ float g_biaso[COUT];

// ---------------- PTX helpers (target-generic only) ----------------
__device__ __forceinline__ uint32_t s2u(const void* p) {
    uint32_t a;
    asm("{ .reg .u64 t; cvta.to.shared.u64 t, %1; cvt.u32.u64 %0, t; }" : "=r"(a) : "l"(p));
    return a;
}
__device__ __forceinline__ void cp16(uint32_t dst, const void* src) {
    asm volatile("cp.async.cg.shared.global [%0], [%1], 16;" :: "r"(dst), "l"(src));
}
__device__ __forceinline__ void cp_commit() {
    asm volatile("cp.async.commit_group;" ::: "memory");
}
__device__ __forceinline__ void cp_wait1() {
    asm volatile("cp.async.wait_group 1;" ::: "memory");
}
__device__ __forceinline__ void ldsm4(uint32_t* r, uint32_t a) {
    asm volatile("ldmatrix.sync.aligned.m8n8.x4.shared.b16 {%0,%1,%2,%3}, [%4];"
                 : "=r"(r[0]), "=r"(r[1]), "=r"(r[2]), "=r"(r[3]) : "r"(a));
}
__device__ __forceinline__ void ldsm4t(uint32_t* r, uint32_t a) {
    asm volatile("ldmatrix.sync.aligned.m8n8.x4.trans.shared.b16 {%0,%1,%2,%3}, [%4];"
                 : "=r"(r[0]), "=r"(r[1]), "=r"(r[2]), "=r"(r[3]) : "r"(a));
}
__device__ __forceinline__ void mma16816(float* d, const uint32_t* a, uint32_t b0, uint32_t b1) {
    asm volatile(
        "mma.sync.aligned.m16n8k16.row.col.f32.f16.f16.f32 "
        "{%0,%1,%2,%3}, {%4,%5,%6,%7}, {%8,%9}, {%0,%1,%2,%3};"
        : "+f"(d[0]), "+f"(d[1]), "+f"(d[2]), "+f"(d[3])
        : "r"(a[0]), "r"(a[1]), "r"(a[2]), "r"(a[3]), "r"(b0), "r"(b1));
}

// ---------------- Kernel A: Haar bands -> fp16 + partial stats ----------------
// grid (256 channels, 2 half-planes); block: 512 threads, 64 output rows.
// Per iteration: 2 pixel-pairs from disjoint quadrants (MLP=4 loads). R11 body.
__global__ __launch_bounds__(512) void haar_kernel(const float* __restrict__ x) {
    const int cx    = blockIdx.x;            // input channel 0..255
    const int chunk = blockIdx.y;            // 0..1
    const float* xp = x + (size_t)cx * (HDIM * WDIM);

    float s0=0.f,s1=0.f,s2=0.f,s3=0.f,q0=0.f,q1=0.f,q2=0.f,q3=0.f;

    const int base = chunk * 8192;
    for (int t = threadIdx.x * 2; t < 4096; t += 1024) {
        const int iA = base + t;             // quadrant A
        const int iB = iA + 4096;            // quadrant B
        const int hA = iA >> 7, wA = iA & 127;
        const int hB = iB >> 7, wB = iB & 127;
        // 4 independent loads up front
        const float4 a0 = *(const float4*)(xp + (size_t)(2*hA)   * WDIM + 2*wA);
        const float4 a1 = *(const float4*)(xp + (size_t)(2*hA+1) * WDIM + 2*wA);
        const float4 b0 = *(const float4*)(xp + (size_t)(2*hB)   * WDIM + 2*wB);
        const float4 b1 = *(const float4*)(xp + (size_t)(2*hB+1) * WDIM + 2*wB);

        float vA0[4], vA1[4], vB0[4], vB1[4];
        vA0[0] = 0.5f*( a0.x + a0.y + a1.x + a1.y);
        vA0[1] = 0.5f*(-a0.x - a0.y + a1.x + a1.y);
        vA0[2] = 0.5f*(-a0.x + a0.y - a1.x + a1.y);
        vA0[3] = 0.5f*( a0.x - a0.y - a1.x + a1.y);
        vA1[0] = 0.5f*( a0.z + a0.w + a1.z + a1.w);
        vA1[1] = 0.5f*(-a0.z - a0.w + a1.z + a1.w);
        vA1[2] = 0.5f*(-a0.z + a0.w - a1.z + a1.w);
        vA1[3] = 0.5f*( a0.z - a0.w - a1.z + a1.w);
        vB0[0] = 0.5f*( b0.x + b0.y + b1.x + b1.y);
        vB0[1] = 0.5f*(-b0.x - b0.y + b1.x + b1.y);
        vB0[2] = 0.5f*(-b0.x + b0.y - b1.x + b1.y);
        vB0[3] = 0.5f*( b0.x - b0.y - b1.x + b1.y);
        vB1[0] = 0.5f*( b0.z + b0.w + b1.z + b1.w);
        vB1[1] = 0.5f*(-b0.z - b0.w + b1.z + b1.w);
        vB1[2] = 0.5f*(-b0.z + b0.w - b1.z + b1.w);
        vB1[3] = 0.5f*( b0.z - b0.w - b1.z + b1.w);

        #pragma unroll
        for (int b = 0; b < 4; b++) {
            const size_t c = (size_t)b * 256 + cx;
            *(__half2*)&g_B[c * HW + iA] =
                __halves2half2(__float2half_rn(vA0[b]), __float2half_rn(vA1[b]));
            *(__half2*)&g_B[c * HW + iB] =
                __halves2half2(__float2half_rn(vB0[b]), __float2half_rn(vB1[b]));
        }
        s0 += vA0[0]+vA1[0]+vB0[0]+vB1[0];
        q0 += vA0[0]*vA0[0]+vA1[0]*vA1[0]+vB0[0]*vB0[0]+vB1[0]*vB1[0];
        s1 += vA0[1]+vA1[1]+vB0[1]+vB1[1];
        q1 += vA0[1]*vA0[1]+vA1[1]*vA1[1]+vB0[1]*vB0[1]+vB1[1]*vB1[1];
        s2 += vA0[2]+vA1[2]+vB0[2]+vB1[2];
        q2 += vA0[2]*vA0[2]+vA1[2]*vA1[2]+vB0[2]*vB0[2]+vB1[2]*vB1[2];
        s3 += vA0[3]+vA1[3]+vB0[3]+vB1[3];
        q3 += vA0[3]*vA0[3]+vA1[3]*vA1[3]+vB0[3]*vB0[3]+vB1[3]*vB1[3];
    }

    // warp shuffle reduce 8 values, then one smem stage
    float vals[8] = {s0,s1,s2,s3,q0,q1,q2,q3};
    #pragma unroll
    for (int q = 0; q < 8; q++) {
        #pragma unroll
        for (int off = 16; off > 0; off >>= 1)
            vals[q] += __shfl_xor_sync(0xFFFFFFFFu, vals[q], off);
    }
    __shared__ float wred[16][8];            // [warp][metric]
    const int wid = threadIdx.x >> 5;
    const int lid = threadIdx.x & 31;
    if (lid == 0) {
        #pragma unroll
        for (int q = 0; q < 8; q++) wred[wid][q] = vals[q];
    }
    __syncthreads();
    if (threadIdx.x < 8) {
        const int q = threadIdx.x;
        float r = 0.f;
        #pragma unroll
        for (int w = 0; w < 16; w++) r += wred[w][q];
        const int band = q & 3;
        const int idx = chunk * KB + band * 256 + cx;
        if (q < 4) g_psum[idx]   = r;
        else       g_psumsq[idx] = r;
    }
}

// ---------------- Kernel B: stats + fold affine into fp16 weights ------
__global__ __launch_bounds__(256) void foldw_kernel(const float* __restrict__ w,
                                                    const float* __restrict__ scale,
                                                    const float* __restrict__ bias) {
    __shared__ float sa[KB], sb[KB];
    const int tid = threadIdx.x;
    if (tid < NGROUP) {
        const int g = tid;
        float s = 0.f, q = 0.f;
        #pragma unroll
        for (int j = 0; j < GSIZE; j++) {
            const int c = g*GSIZE + j;
            #pragma unroll
            for (int ch = 0; ch < 2; ch++) {
                s += g_psum[ch * KB + c];
                q += g_psumsq[ch * KB + c];
            }
        }
        const float inv  = 1.0f / (float)(GSIZE * HW);
        const float mean = s * inv;
        const float var  = q * inv - mean * mean;
        const float rstd = rsqrtf(var + GN_EPS);
        #pragma unroll
        for (int j = 0; j < GSIZE; j++) {
            const int c = g*GSIZE + j;
            const float a = scale[c] * rstd;
            sa[c] = a;
            sb[c] = bias[c] - mean * a;
        }
    }
    __syncthreads();

    const int o = blockIdx.x;                // 0..511
    float part = 0.f;
    for (int c = tid; c < KB; c += 256) {
        const float wv = w[(size_t)o * KB + c];
        g_A[(size_t)o * KB + c] = __float2half_rn(wv * sa[c]);
        part += wv * sb[c];
    }
    __shared__ float red[256];
    red[tid] = part;
    __syncthreads();
    for (int off = 128; off > 0; off >>= 1) {
        if (tid < off) red[tid] += red[tid + off];
        __syncthreads();
    }
    if (tid == 0) g_biaso[o] = red[0];
}

// ---------------- Kernel C: mma.sync fp16 GEMM + bias + ReLU (R9-best) ----
// CTA tile 128(M) x 64(N), BK=64; 8 warps, warp tile 32x32 (4x2 warp grid).
// Stage: A 16KB + B 8KB = 24KB; 3 stages = 72KB. 3 CTAs/SM (24 warps).
#define STAGE_BYTES 24576
#define GEMM_SMEM   (3 * STAGE_BYTES)

__device__ __forceinline__ void load_stage(int tid, int j, uint32_t sbase, int m0, int n0) {
    const uint32_t st = sbase + (uint32_t)(j % 3) * STAGE_BYTES;
    const int koff = j << 6;                 // 0..960
    const __half* Ab = g_A + (size_t)m0 * KB + koff;
    const __half* Bb = g_B + (size_t)koff * HW + n0;
    // A: 128 rows(m) x 8 chunks(kc of 8 halves); unit = m*8 + (kc ^ (m&7))
    #pragma unroll
    for (int t = 0; t < 4; t++) {
        const int u = tid + t * 256;
        const int m = u >> 3, kc = u & 7;
        const uint32_t du = (uint32_t)(m * 8 + (kc ^ (m & 7))) * 16;
        cp16(st + du, Ab + (size_t)m * KB + kc * 8);
    }
    // B: 64 rows(k) x 8 chunks(nc of 8 halves); unit = k*8 + (nc ^ (k&7))
    #pragma unroll
    for (int t = 0; t < 2; t++) {
        const int u = tid + t * 256;
        const int k = u >> 3, nc = u & 7;
        const uint32_t du = (uint32_t)(k * 8 + (nc ^ (k & 7)));
        cp16(st + 16384 + du * 16, Bb + (size_t)k * HW + nc * 8);
    }
}

__global__ __launch_bounds__(256, 3) void gemm_mma_kernel(float* __restrict__ out) {
    extern __shared__ char smem[];
    const uint32_t sbase = s2u(smem);
    const int tid  = threadIdx.x;
    const int wid  = tid >> 5;
    const int lane = tid & 31;
    const int n0 = blockIdx.x * 64;
    const int m0 = blockIdx.y * 128;
    const int wm = wid >> 1;                 // 0..3
    const int wn = wid & 1;                  // 0..1
    const int mbase = wm * 32;
    const int nbase = wn * 32;

    const int r15 = lane & 15;
    const int hi  = lane >> 4;
    const int s7  = r15 & 7;

    float acc[2][4][4];
    #pragma unroll
    for (int i = 0; i < 2; i++)
        #pragma unroll
        for (int j = 0; j < 4; j++)
            #pragma unroll
            for (int q = 0; q < 4; q++) acc[i][j][q] = 0.f;

    load_stage(tid, 0, sbase, m0, n0); cp_commit();
    load_stage(tid, 1, sbase, m0, n0); cp_commit();

    for (int j = 0; j < TITER; j++) {
        cp_wait1();
        __syncthreads();
        if (j + 2 < TITER) load_stage(tid, j + 2, sbase, m0, n0);
        cp_commit();

        const uint32_t st = sbase + (uint32_t)(j % 3) * STAGE_BYTES;
        #pragma unroll
        for (int kk = 0; kk < 4; kk++) {
            uint32_t b[2][4];
            #pragma unroll
            for (int p = 0; p < 2; p++) {
                const int k   = kk * 16 + r15;
                const int ncg = wn * 4 + p * 2 + hi;
                ldsm4t(b[p], st + 16384 + (uint32_t)((k * 8 + (ncg ^ s7)) * 16));
            }
            uint32_t a[2][4];
            #pragma unroll
            for (int mf = 0; mf < 2; mf++) {
                const int row = mbase + mf * 16 + r15;
                ldsm4(a[mf], st + (uint32_t)(row * 128) + (uint32_t)(((kk * 2 + hi) ^ s7) * 16));
            }
            #pragma unroll
            for (int mf = 0; mf < 2; mf++)
                #pragma unroll
                for (int nf = 0; nf < 4; nf++)
                    mma16816(acc[mf][nf], a[mf], b[nf >> 1][(nf & 1) * 2],
                             b[nf >> 1][(nf & 1) * 2 + 1]);
        }
    }

    // epilogue: bias + ReLU + float2 stores
    const int qrow = lane >> 2;
    const int qcol = (lane & 3) * 2;
    #pragma unroll
    for (int mf = 0; mf < 2; mf++) {
        const int row0 = m0 + mbase + mf * 16 + qrow;
        const float bi0 = g_biaso[row0];
        const float bi1 = g_biaso[row0 + 8];
        float* o0 = out + (size_t)row0 * HW + n0 + nbase + qcol;
        float* o1 = out + (size_t)(row0 + 8) * HW + n0 + nbase + qcol;
        #pragma unroll
        for (int nf = 0; nf < 4; nf++) {
            float2 v0, v1;
            v0.x = fmaxf(acc[mf][nf][0] + bi0, 0.f);
            v0.y = fmaxf(acc[mf][nf][1] + bi0, 0.f);
            v1.x = fmaxf(acc[mf][nf][2] + bi1, 0.f);
            v1.y = fmaxf(acc[mf][nf][3] + bi1, 0.f);
            *(float2*)(o0 + nf * 8) = v0;
            *(float2*)(o1 + nf * 8) = v1;
        }
    }
}

// ---------------- launch ----------------
extern "C" void kernel_launch(void* const* d_in, const int* in_sizes, int n_in,
                              void* d_out, int out_size) {
    const float* x        = (const float*)d_in[0];
    const float* gn_scale = (const float*)d_in[1];
    const float* gn_bias  = (const float*)d_in[2];
    const float* w_proj   = (const float*)d_in[3];
    float* out = (float*)d_out;

    cudaFuncSetAttribute(gemm_mma_kernel,
                         cudaFuncAttributeMaxDynamicSharedMemorySize, GEMM_SMEM);

    dim3 hgrid(256, 2);
    haar_kernel<<<hgrid, 512>>>(x);
    foldw_kernel<<<COUT, 256>>>(w_proj, gn_scale, gn_bias);
    dim3 grid(HW / 64, COUT / 128);
    gemm_mma_kernel<<<grid, 256, GEMM_SMEM>>>(out);
}

// round 14
// speedup vs baseline: 1.0694x; 1.0312x over previous
#include <cuda_runtime.h>
#include <cuda_fp16.h>
#include <cstdint>

// ---------------- problem constants ----------------
#define HDIM   256
#define WDIM   256
#define HW     16384          // 128*128 output pixels
#define KB     1024           // K (channels)
#define COUT   512
#define NGROUP 128
#define GSIZE  8
#define GN_EPS 1e-5f
#define TITER  16             // 1024 / 64

// ---------------- device scratch ----------------
__device__ __half g_B[(size_t)KB * HW];        // 32 MB: Y fp16, [k][n]
__device__ __half g_A[(size_t)COUT * KB];      // 1 MB: folded W fp16, [o][k]
__device__ float g_psum[2 * KB];               // per-chunk partial sums
__device__ float g_psumsq[2 * KB];
__device__ float g_biaso[COUT];

// ---------------- PTX helpers (target-generic only) ----------------
__device__ __forceinline__ uint32_t s2u(const void* p) {
    uint32_t a;
    asm("{ .reg .u64 t; cvta.to.shared.u64 t, %1; cvt.u32.u64 %0, t; }" : "=r"(a) : "l"(p));
    return a;
}
__device__ __forceinline__ void cp16(uint32_t dst, const void* src) {
    asm volatile("cp.async.cg.shared.global [%0], [%1], 16;" :: "r"(dst), "l"(src));
}
__device__ __forceinline__ void cp_commit() {
    asm volatile("cp.async.commit_group;" ::: "memory");
}
__device__ __forceinline__ void cp_wait1() {
    asm volatile("cp.async.wait_group 1;" ::: "memory");
}
__device__ __forceinline__ void ldsm4(uint32_t* r, uint32_t a) {
    asm volatile("ldmatrix.sync.aligned.m8n8.x4.shared.b16 {%0,%1,%2,%3}, [%4];"
                 : "=r"(r[0]), "=r"(r[1]), "=r"(r[2]), "=r"(r[3]) : "r"(a));
}
__device__ __forceinline__ void ldsm4t(uint32_t* r, uint32_t a) {
    asm volatile("ldmatrix.sync.aligned.m8n8.x4.trans.shared.b16 {%0,%1,%2,%3}, [%4];"
                 : "=r"(r[0]), "=r"(r[1]), "=r"(r[2]), "=r"(r[3]) : "r"(a));
}
__device__ __forceinline__ void mma16816(float* d, const uint32_t* a, uint32_t b0, uint32_t b1) {
    asm volatile(
        "mma.sync.aligned.m16n8k16.row.col.f32.f16.f16.f32 "
        "{%0,%1,%2,%3}, {%4,%5,%6,%7}, {%8,%9}, {%0,%1,%2,%3};"
        : "+f"(d[0]), "+f"(d[1]), "+f"(d[2]), "+f"(d[3])
        : "r"(a[0]), "r"(a[1]), "r"(a[2]), "r"(a[3]), "r"(b0), "r"(b1));
}

// ---------------- Kernel A: Haar bands -> fp16 + partial stats ----------------
// grid (256 channels, 2 half-planes) x 256 threads; 4 iterations/thread.
// Per iteration: 4 consecutive px in quadrant A + 4 in quadrant B
// -> 8 independent float4 loads (8 sectors in flight), 8 x STG.64 stores.
__device__ __forceinline__ void haar4(const float4& r0a, const float4& r0b,
                                      const float4& r1a, const float4& r1b,
                                      float v[4][4]) {
    const float p00[4] = {r0a.x, r0a.z, r0b.x, r0b.z};
    const float p01[4] = {r0a.y, r0a.w, r0b.y, r0b.w};
    const float p10[4] = {r1a.x, r1a.z, r1b.x, r1b.z};
    const float p11[4] = {r1a.y, r1a.w, r1b.y, r1b.w};
    #pragma unroll
    for (int p = 0; p < 4; p++) {
        v[0][p] = 0.5f*( p00[p] + p01[p] + p10[p] + p11[p]);
        v[1][p] = 0.5f*(-p00[p] - p01[p] + p10[p] + p11[p]);
        v[2][p] = 0.5f*(-p00[p] + p01[p] - p10[p] + p11[p]);
        v[3][p] = 0.5f*( p00[p] - p01[p] - p10[p] + p11[p]);
    }
}

__global__ __launch_bounds__(256) void haar_kernel(const float* __restrict__ x) {
    const int cx    = blockIdx.x;            // input channel 0..255
    const int chunk = blockIdx.y;            // 0..1
    const float* xp = x + (size_t)cx * (HDIM * WDIM);

    float s[4] = {0.f, 0.f, 0.f, 0.f};
    float q[4] = {0.f, 0.f, 0.f, 0.f};

    const int base = chunk * 8192;
    for (int t = threadIdx.x * 4; t < 4096; t += 1024) {
        const int iA = base + t;             // quadrant A (4 px)
        const int iB = iA + 4096;            // quadrant B (4 px)
        const int hA = iA >> 7, wA = iA & 127;   // wA multiple of 4
        const int hB = iB >> 7, wB = iB & 127;
        const float* rA0 = xp + (size_t)(2*hA)   * WDIM + 2*wA;
        const float* rA1 = xp + (size_t)(2*hA+1) * WDIM + 2*wA;
        const float* rB0 = xp + (size_t)(2*hB)   * WDIM + 2*wB;
        const float* rB1 = xp + (size_t)(2*hB+1) * WDIM + 2*wB;
        // 8 independent loads issued up front
        const float4 a00 = *(const float4*)(rA0);
        const float4 a01 = *(const float4*)(rA0 + 4);
        const float4 a10 = *(const float4*)(rA1);
        const float4 a11 = *(const float4*)(rA1 + 4);
        const float4 b00 = *(const float4*)(rB0);
        const float4 b01 = *(const float4*)(rB0 + 4);
        const float4 b10 = *(const float4*)(rB1);
        const float4 b11 = *(const float4*)(rB1 + 4);

        float vA[4][4], vB[4][4];            // [band][px]
        haar4(a00, a01, a10, a11, vA);
        haar4(b00, b01, b10, b11, vB);

        #pragma unroll
        for (int b = 0; b < 4; b++) {
            const size_t c = (size_t)b * 256 + cx;
            const __half2 hA01 = __halves2half2(__float2half_rn(vA[b][0]), __float2half_rn(vA[b][1]));
            const __half2 hA23 = __halves2half2(__float2half_rn(vA[b][2]), __float2half_rn(vA[b][3]));
            const __half2 hB01 = __halves2half2(__float2half_rn(vB[b][0]), __float2half_rn(vB[b][1]));
            const __half2 hB23 = __halves2half2(__float2half_rn(vB[b][2]), __float2half_rn(vB[b][3]));
            uint2 stA, stB;
            stA.x = *(const uint32_t*)&hA01; stA.y = *(const uint32_t*)&hA23;
            stB.x = *(const uint32_t*)&hB01; stB.y = *(const uint32_t*)&hB23;
            *(uint2*)&g_B[c * HW + iA] = stA;
            *(uint2*)&g_B[c * HW + iB] = stB;
            #pragma unroll
            for (int p = 0; p < 4; p++) {
                s[b] += vA[b][p] + vB[b][p];
                q[b] += vA[b][p]*vA[b][p] + vB[b][p]*vB[b][p];
            }
        }
    }

    // warp shuffle reduce 8 values, then one smem stage
    float vals[8] = {s[0],s[1],s[2],s[3],q[0],q[1],q[2],q[3]};
    #pragma unroll
    for (int m = 0; m < 8; m++) {
        #pragma unroll
        for (int off = 16; off > 0; off >>= 1)
            vals[m] += __shfl_xor_sync(0xFFFFFFFFu, vals[m], off);
    }
    __shared__ float wred[8][8];             // [warp][metric]
    const int wid = threadIdx.x >> 5;
    const int lid = threadIdx.x & 31;
    if (lid == 0) {
        #pragma unroll
        for (int m = 0; m < 8; m++) wred[wid][m] = vals[m];
    }
    __syncthreads();
    if (threadIdx.x < 8) {
        const int m = threadIdx.x;
        float r = 0.f;
        #pragma unroll
        for (int w = 0; w < 8; w++) r += wred[w][m];
        const int band = m & 3;
        const int idx = chunk * KB + band * 256 + cx;
        if (m < 4) g_psum[idx]   = r;
        else       g_psumsq[idx] = r;
    }
}

// ---------------- Kernel B: stats + fold affine into fp16 weights ------
__global__ __launch_bounds__(256) void foldw_kernel(const float* __restrict__ w,
                                                    const float* __restrict__ scale,
                                                    const float* __restrict__ bias) {
    __shared__ float sa[KB], sb[KB];
    const int tid = threadIdx.x;
    if (tid < NGROUP) {
        const int g = tid;
        float s = 0.f, q = 0.f;
        #pragma unroll
        for (int j = 0; j < GSIZE; j++) {
            const int c = g*GSIZE + j;
            #pragma unroll
            for (int ch = 0; ch < 2; ch++) {
                s += g_psum[ch * KB + c];
                q += g_psumsq[ch * KB + c];
            }
        }
        const float inv  = 1.0f / (float)(GSIZE * HW);
        const float mean = s * inv;
        const float var  = q * inv - mean * mean;
        const float rstd = rsqrtf(var + GN_EPS);
        #pragma unroll
        for (int j = 0; j < GSIZE; j++) {
            const int c = g*GSIZE + j;
            const float a = scale[c] * rstd;
            sa[c] = a;
            sb[c] = bias[c] - mean * a;
        }
    }
    __syncthreads();

    const int o = blockIdx.x;                // 0..511
    float part = 0.f;
    for (int c = tid; c < KB; c += 256) {
        const float wv = w[(size_t)o * KB + c];
        g_A[(size_t)o * KB + c] = __float2half_rn(wv * sa[c]);
        part += wv * sb[c];
    }
    __shared__ float red[256];
    red[tid] = part;
    __syncthreads();
    for (int off = 128; off > 0; off >>= 1) {
        if (tid < off) red[tid] += red[tid + off];
        __syncthreads();
    }
    if (tid == 0) g_biaso[o] = red[0];
}

// ---------------- Kernel C: mma.sync fp16 GEMM + bias + ReLU (R9-best) ----
// CTA tile 128(M) x 64(N), BK=64; 8 warps, warp tile 32x32 (4x2 warp grid).
// Stage: A 16KB + B 8KB = 24KB; 3 stages = 72KB. 3 CTAs/SM (24 warps).
#define STAGE_BYTES 24576
#define GEMM_SMEM   (3 * STAGE_BYTES)

__device__ __forceinline__ void load_stage(int tid, int j, uint32_t sbase, int m0, int n0) {
    const uint32_t st = sbase + (uint32_t)(j % 3) * STAGE_BYTES;
    const int koff = j << 6;                 // 0..960
    const __half* Ab = g_A + (size_t)m0 * KB + koff;
    const __half* Bb = g_B + (size_t)koff * HW + n0;
    // A: 128 rows(m) x 8 chunks(kc of 8 halves); unit = m*8 + (kc ^ (m&7))
    #pragma unroll
    for (int t = 0; t < 4; t++) {
        const int u = tid + t * 256;
        const int m = u >> 3, kc = u & 7;
        const uint32_t du = (uint32_t)(m * 8 + (kc ^ (m & 7))) * 16;
        cp16(st + du, Ab + (size_t)m * KB + kc * 8);
    }
    // B: 64 rows(k) x 8 chunks(nc of 8 halves); unit = k*8 + (nc ^ (k&7))
    #pragma unroll
    for (int t = 0; t < 2; t++) {
        const int u = tid + t * 256;
        const int k = u >> 3, nc = u & 7;
        const uint32_t du = (uint32_t)(k * 8 + (nc ^ (k & 7)));
        cp16(st + 16384 + du * 16, Bb + (size_t)k * HW + nc * 8);
    }
}

__global__ __launch_bounds__(256, 3) void gemm_mma_kernel(float* __restrict__ out) {
    extern __shared__ char smem[];
    const uint32_t sbase = s2u(smem);
    const int tid  = threadIdx.x;
    const int wid  = tid >> 5;
    const int lane = tid & 31;
    const int n0 = blockIdx.x * 64;
    const int m0 = blockIdx.y * 128;
    const int wm = wid >> 1;                 // 0..3
    const int wn = wid & 1;                  // 0..1
    const int mbase = wm * 32;
    const int nbase = wn * 32;

    const int r15 = lane & 15;
    const int hi  = lane >> 4;
    const int s7  = r15 & 7;

    float acc[2][4][4];
    #pragma unroll
    for (int i = 0; i < 2; i++)
        #pragma unroll
        for (int j = 0; j < 4; j++)
            #pragma unroll
            for (int q = 0; q < 4; q++) acc[i][j][q] = 0.f;

    load_stage(tid, 0, sbase, m0, n0); cp_commit();
    load_stage(tid, 1, sbase, m0, n0); cp_commit();

    for (int j = 0; j < TITER; j++) {
        cp_wait1();
        __syncthreads();
        if (j + 2 < TITER) load_stage(tid, j + 2, sbase, m0, n0);
        cp_commit();

        const uint32_t st = sbase + (uint32_t)(j % 3) * STAGE_BYTES;
        #pragma unroll
        for (int kk = 0; kk < 4; kk++) {
            uint32_t b[2][4];
            #pragma unroll
            for (int p = 0; p < 2; p++) {
                const int k   = kk * 16 + r15;
                const int ncg = wn * 4 + p * 2 + hi;
                ldsm4t(b[p], st + 16384 + (uint32_t)((k * 8 + (ncg ^ s7)) * 16));
            }
            uint32_t a[2][4];
            #pragma unroll
            for (int mf = 0; mf < 2; mf++) {
                const int row = mbase + mf * 16 + r15;
                ldsm4(a[mf], st + (uint32_t)(row * 128) + (uint32_t)(((kk * 2 + hi) ^ s7) * 16));
            }
            #pragma unroll
            for (int mf = 0; mf < 2; mf++)
                #pragma unroll
                for (int nf = 0; nf < 4; nf++)
                    mma16816(acc[mf][nf], a[mf], b[nf >> 1][(nf & 1) * 2],
                             b[nf >> 1][(nf & 1) * 2 + 1]);
        }
    }

    // epilogue: bias + ReLU + float2 stores
    const int qrow = lane >> 2;
    const int qcol = (lane & 3) * 2;
    #pragma unroll
    for (int mf = 0; mf < 2; mf++) {
        const int row0 = m0 + mbase + mf * 16 + qrow;
        const float bi0 = g_biaso[row0];
        const float bi1 = g_biaso[row0 + 8];
        float* o0 = out + (size_t)row0 * HW + n0 + nbase + qcol;
        float* o1 = out + (size_t)(row0 + 8) * HW + n0 + nbase + qcol;
        #pragma unroll
        for (int nf = 0; nf < 4; nf++) {
            float2 v0, v1;
            v0.x = fmaxf(acc[mf][nf][0] + bi0, 0.f);
            v0.y = fmaxf(acc[mf][nf][1] + bi0, 0.f);
            v1.x = fmaxf(acc[mf][nf][2] + bi1, 0.f);
            v1.y = fmaxf(acc[mf][nf][3] + bi1, 0.f);
            *(float2*)(o0 + nf * 8) = v0;
            *(float2*)(o1 + nf * 8) = v1;
        }
    }
}

// ---------------- launch ----------------
extern "C" void kernel_launch(void* const* d_in, const int* in_sizes, int n_in,
                              void* d_out, int out_size) {
    const float* x        = (const float*)d_in[0];
    const float* gn_scale = (const float*)d_in[1];
    const float* gn_bias  = (const float*)d_in[2];
    const float* w_proj   = (const float*)d_in[3];
    float* out = (float*)d_out;

    cudaFuncSetAttribute(gemm_mma_kernel,
                         cudaFuncAttributeMaxDynamicSharedMemorySize, GEMM_SMEM);

    dim3 hgrid(256, 2);
    haar_kernel<<<hgrid, 256>>>(x);
    foldw_kernel<<<COUT, 256>>>(w_proj, gn_scale, gn_bias);
    dim3 grid(HW / 64, COUT / 128);
    gemm_mma_kernel<<<grid, 256, GEMM_SMEM>>>(out);
}

// round 15
// speedup vs baseline: 1.0927x; 1.0218x over previous
#include <cuda_runtime.h>
#include <cuda_fp16.h>
#include <cstdint>

// ---------------- problem constants ----------------
#define HDIM   256
#define WDIM   256
#define HW     16384          // 128*128 output pixels
#define KB     1024           // K (channels)
#define COUT   512
#define NGROUP 128
#define GSIZE  8
#define GN_EPS 1e-5f
#define TITER  16             // 1024 / 64

// ---------------- device scratch ----------------
__device__ __half g_B[(size_t)KB * HW];        // 32 MB: Y fp16, [k][n]
__device__ __half g_A[(size_t)COUT * KB];      // 1 MB: folded W fp16, [o][k]
__device__ float g_psum[2 * KB];               // per-chunk partial sums
__device__ float g_psumsq[2 * KB];
__device__ float g_biaso[COUT];

// ---------------- PTX helpers (target-generic only) ----------------
__device__ __forceinline__ uint32_t s2u(const void* p) {
    uint32_t a;
    asm("{ .reg .u64 t; cvta.to.shared.u64 t, %1; cvt.u32.u64 %0, t; }" : "=r"(a) : "l"(p));
    return a;
}
__device__ __forceinline__ void cp16(uint32_t dst, const void* src) {
    asm volatile("cp.async.cg.shared.global [%0], [%1], 16;" :: "r"(dst), "l"(src));
}
__device__ __forceinline__ void cp_commit() {
    asm volatile("cp.async.commit_group;" ::: "memory");
}
__device__ __forceinline__ void cp_wait1() {
    asm volatile("cp.async.wait_group 1;" ::: "memory");
}
__device__ __forceinline__ void gdc_wait() {
    asm volatile("griddepcontrol.wait;" ::: "memory");
}
__device__ __forceinline__ void ldsm4(uint32_t* r, uint32_t a) {
    asm volatile("ldmatrix.sync.aligned.m8n8.x4.shared.b16 {%0,%1,%2,%3}, [%4];"
                 : "=r"(r[0]), "=r"(r[1]), "=r"(r[2]), "=r"(r[3]) : "r"(a));
}
__device__ __forceinline__ void ldsm4t(uint32_t* r, uint32_t a) {
    asm volatile("ldmatrix.sync.aligned.m8n8.x4.trans.shared.b16 {%0,%1,%2,%3}, [%4];"
                 : "=r"(r[0]), "=r"(r[1]), "=r"(r[2]), "=r"(r[3]) : "r"(a));
}
__device__ __forceinline__ void mma16816(float* d, const uint32_t* a, uint32_t b0, uint32_t b1) {
    asm volatile(
        "mma.sync.aligned.m16n8k16.row.col.f32.f16.f16.f32 "
        "{%0,%1,%2,%3}, {%4,%5,%6,%7}, {%8,%9}, {%0,%1,%2,%3};"
        : "+f"(d[0]), "+f"(d[1]), "+f"(d[2]), "+f"(d[3])
        : "r"(a[0]), "r"(a[1]), "r"(a[2]), "r"(a[3]), "r"(b0), "r"(b1));
}

// ---------------- Kernel A: Haar bands -> fp16 + partial stats (v5) ----------
// grid (256 channels, 2 half-planes) x 256 threads; 4 iterations/thread.
// Per iteration: 8 consecutive output px (one row segment) -> 8 independent
// float4 loads (MLP=8), one STG.128 per band.
__global__ __launch_bounds__(256) void haar_kernel(const float* __restrict__ x) {
    const int cx    = blockIdx.x;            // input channel 0..255
    const int chunk = blockIdx.y;            // 0..1
    const float* xp = x + (size_t)cx * (HDIM * WDIM);

    float s[4] = {0.f, 0.f, 0.f, 0.f};
    float q[4] = {0.f, 0.f, 0.f, 0.f};

    const int base = chunk * 8192;
    for (int t = threadIdx.x * 8; t < 8192; t += 2048) {   // 4 iterations
        const int i = base + t;
        const int h = i >> 7, w = i & 127;   // w multiple of 8
        const float* r0 = xp + (size_t)(2*h)   * WDIM + 2*w;
        const float* r1 = xp + (size_t)(2*h+1) * WDIM + 2*w;
        // 8 independent float4 loads
        float4 a[4], b[4];
        #pragma unroll
        for (int j = 0; j < 4; j++) {
            a[j] = *(const float4*)(r0 + 4*j);
            b[j] = *(const float4*)(r1 + 4*j);
        }
        const float* af = (const float*)a;
        const float* bf = (const float*)b;

        uint32_t pk[4][4];                   // [band][px-pair] half2 words
        #pragma unroll
        for (int p = 0; p < 8; p++) {
            const float x00 = af[2*p], x01 = af[2*p+1];
            const float x10 = bf[2*p], x11 = bf[2*p+1];
            float v[4];
            v[0] = 0.5f*( x00 + x01 + x10 + x11);
            v[1] = 0.5f*(-x00 - x01 + x10 + x11);
            v[2] = 0.5f*(-x00 + x01 - x10 + x11);
            v[3] = 0.5f*( x00 - x01 - x10 + x11);
            #pragma unroll
            for (int bd = 0; bd < 4; bd++) {
                s[bd] += v[bd];
                q[bd] += v[bd] * v[bd];
                const uint32_t hbits = (uint32_t)__half_as_ushort(__float2half_rn(v[bd]));
                if ((p & 1) == 0) pk[bd][p >> 1] = hbits;
                else              pk[bd][p >> 1] |= hbits << 16;
            }
        }
        #pragma unroll
        for (int bd = 0; bd < 4; bd++) {
            const size_t c = (size_t)bd * 256 + cx;
            uint4 st;
            st.x = pk[bd][0]; st.y = pk[bd][1];
            st.z = pk[bd][2]; st.w = pk[bd][3];
            *(uint4*)&g_B[c * HW + i] = st;  // i % 8 == 0 -> 16B aligned
        }
    }

    // warp shuffle reduce 8 values, then one smem stage
    float vals[8] = {s[0],s[1],s[2],s[3],q[0],q[1],q[2],q[3]};
    #pragma unroll
    for (int m = 0; m < 8; m++) {
        #pragma unroll
        for (int off = 16; off > 0; off >>= 1)
            vals[m] += __shfl_xor_sync(0xFFFFFFFFu, vals[m], off);
    }
    __shared__ float wred[8][8];             // [warp][metric]
    const int wid = threadIdx.x >> 5;
    const int lid = threadIdx.x & 31;
    if (lid == 0) {
        #pragma unroll
        for (int m = 0; m < 8; m++) wred[wid][m] = vals[m];
    }
    __syncthreads();
    if (threadIdx.x < 8) {
        const int m = threadIdx.x;
        float r = 0.f;
        #pragma unroll
        for (int w2 = 0; w2 < 8; w2++) r += wred[w2][m];
        const int band = m & 3;
        const int idx = chunk * KB + band * 256 + cx;
        if (m < 4) g_psum[idx]   = r;
        else       g_psumsq[idx] = r;
    }
}

// ---------------- Kernel B: stats + fold affine into fp16 weights (PDL) ------
__global__ __launch_bounds__(256) void foldw_kernel(const float* __restrict__ w,
                                                    const float* __restrict__ scale,
                                                    const float* __restrict__ bias) {
    const int tid = threadIdx.x;
    const int o = blockIdx.x;                // 0..511

    // prefetch w BEFORE waiting on haar (overlaps haar tail via PDL)
    float wv[4];
    #pragma unroll
    for (int t = 0; t < 4; t++) wv[t] = w[(size_t)o * KB + tid + t * 256];

    gdc_wait();                              // haar's psum now visible

    __shared__ float sa[KB], sb[KB];
    if (tid < NGROUP) {
        const int g = tid;
        float s = 0.f, q = 0.f;
        #pragma unroll
        for (int j = 0; j < GSIZE; j++) {
            const int c = g*GSIZE + j;
            #pragma unroll
            for (int ch = 0; ch < 2; ch++) {
                s += g_psum[ch * KB + c];
                q += g_psumsq[ch * KB + c];
            }
        }
        const float inv  = 1.0f / (float)(GSIZE * HW);
        const float mean = s * inv;
        const float var  = q * inv - mean * mean;
        const float rstd = rsqrtf(var + GN_EPS);
        #pragma unroll
        for (int j = 0; j < GSIZE; j++) {
            const int c = g*GSIZE + j;
            const float a = scale[c] * rstd;
            sa[c] = a;
            sb[c] = bias[c] - mean * a;
        }
    }
    __syncthreads();

    float part = 0.f;
    #pragma unroll
    for (int t = 0; t < 4; t++) {
        const int c = tid + t * 256;
        g_A[(size_t)o * KB + c] = __float2half_rn(wv[t] * sa[c]);
        part += wv[t] * sb[c];
    }
    __shared__ float red[256];
    red[tid] = part;
    __syncthreads();
    for (int off = 128; off > 0; off >>= 1) {
        if (tid < off) red[tid] += red[tid + off];
        __syncthreads();
    }
    if (tid == 0) g_biaso[o] = red[0];
}

// ---------------- Kernel C: mma.sync fp16 GEMM + bias + ReLU (R9-best, PDL) ----
// CTA tile 128(M) x 64(N), BK=64; 8 warps, warp tile 32x32 (4x2 warp grid).
// Stage: A 16KB + B 8KB = 24KB; 3 stages = 72KB. 3 CTAs/SM (24 warps).
#define STAGE_BYTES 24576
#define GEMM_SMEM   (3 * STAGE_BYTES)

__device__ __forceinline__ void load_stage(int tid, int j, uint32_t sbase, int m0, int n0) {
    const uint32_t st = sbase + (uint32_t)(j % 3) * STAGE_BYTES;
    const int koff = j << 6;                 // 0..960
    const __half* Ab = g_A + (size_t)m0 * KB + koff;
    const __half* Bb = g_B + (size_t)koff * HW + n0;
    // A: 128 rows(m) x 8 chunks(kc of 8 halves); unit = m*8 + (kc ^ (m&7))
    #pragma unroll
    for (int t = 0; t < 4; t++) {
        const int u = tid + t * 256;
        const int m = u >> 3, kc = u & 7;
        const uint32_t du = (uint32_t)(m * 8 + (kc ^ (m & 7))) * 16;
        cp16(st + du, Ab + (size_t)m * KB + kc * 8);
    }
    // B: 64 rows(k) x 8 chunks(nc of 8 halves); unit = k*8 + (nc ^ (k&7))
    #pragma unroll
    for (int t = 0; t < 2; t++) {
        const int u = tid + t * 256;
        const int k = u >> 3, nc = u & 7;
        const uint32_t du = (uint32_t)(k * 8 + (nc ^ (k & 7)));
        cp16(st + 16384 + du * 16, Bb + (size_t)k * HW + nc * 8);
    }
}

__global__ __launch_bounds__(256, 3) void gemm_mma_kernel(float* __restrict__ out) {
    extern __shared__ char smem[];
    const uint32_t sbase = s2u(smem);
    const int tid  = threadIdx.x;
    const int wid  = tid >> 5;
    const int lane = tid & 31;
    const int n0 = blockIdx.x * 64;
    const int m0 = blockIdx.y * 128;
    const int wm = wid >> 1;                 // 0..3
    const int wn = wid & 1;                  // 0..1
    const int mbase = wm * 32;
    const int nbase = wn * 32;

    const int r15 = lane & 15;
    const int hi  = lane >> 4;
    const int s7  = r15 & 7;

    float acc[2][4][4];
    #pragma unroll
    for (int i = 0; i < 2; i++)
        #pragma unroll
        for (int j = 0; j < 4; j++)
            #pragma unroll
            for (int q = 0; q < 4; q++) acc[i][j][q] = 0.f;

    gdc_wait();                              // foldw (and transitively haar) done

    load_stage(tid, 0, sbase, m0, n0); cp_commit();
    load_stage(tid, 1, sbase, m0, n0); cp_commit();

    for (int j = 0; j < TITER; j++) {
        cp_wait1();
        __syncthreads();
        if (j + 2 < TITER) load_stage(tid, j + 2, sbase, m0, n0);
        cp_commit();

        const uint32_t st = sbase + (uint32_t)(j % 3) * STAGE_BYTES;
        #pragma unroll
        for (int kk = 0; kk < 4; kk++) {
            uint32_t b[2][4];
            #pragma unroll
            for (int p = 0; p < 2; p++) {
                const int k   = kk * 16 + r15;
                const int ncg = wn * 4 + p * 2 + hi;
                ldsm4t(b[p], st + 16384 + (uint32_t)((k * 8 + (ncg ^ s7)) * 16));
            }
            uint32_t a[2][4];
            #pragma unroll
            for (int mf = 0; mf < 2; mf++) {
                const int row = mbase + mf * 16 + r15;
                ldsm4(a[mf], st + (uint32_t)(row * 128) + (uint32_t)(((kk * 2 + hi) ^ s7) * 16));
            }
            #pragma unroll
            for (int mf = 0; mf < 2; mf++)
                #pragma unroll
                for (int nf = 0; nf < 4; nf++)
                    mma16816(acc[mf][nf], a[mf], b[nf >> 1][(nf & 1) * 2],
                             b[nf >> 1][(nf & 1) * 2 + 1]);
        }
    }

    // epilogue: bias + ReLU + float2 stores
    const int qrow = lane >> 2;
    const int qcol = (lane & 3) * 2;
    #pragma unroll
    for (int mf = 0; mf < 2; mf++) {
        const int row0 = m0 + mbase + mf * 16 + qrow;
        const float bi0 = g_biaso[row0];
        const float bi1 = g_biaso[row0 + 8];
        float* o0 = out + (size_t)row0 * HW + n0 + nbase + qcol;
        float* o1 = out + (size_t)(row0 + 8) * HW + n0 + nbase + qcol;
        #pragma unroll
        for (int nf = 0; nf < 4; nf++) {
            float2 v0, v1;
            v0.x = fmaxf(acc[mf][nf][0] + bi0, 0.f);
            v0.y = fmaxf(acc[mf][nf][1] + bi0, 0.f);
            v1.x = fmaxf(acc[mf][nf][2] + bi1, 0.f);
            v1.y = fmaxf(acc[mf][nf][3] + bi1, 0.f);
            *(float2*)(o0 + nf * 8) = v0;
            *(float2*)(o1 + nf * 8) = v1;
        }
    }
}

// ---------------- launch ----------------
extern "C" void kernel_launch(void* const* d_in, const int* in_sizes, int n_in,
                              void* d_out, int out_size) {
    const float* x        = (const float*)d_in[0];
    const float* gn_scale = (const float*)d_in[1];
    const float* gn_bias  = (const float*)d_in[2];
    const float* w_proj   = (const float*)d_in[3];
    float* out = (float*)d_out;

    cudaFuncSetAttribute(gemm_mma_kernel,
                         cudaFuncAttributeMaxDynamicSharedMemorySize, GEMM_SMEM);

    dim3 hgrid(256, 2);
    haar_kernel<<<hgrid, 256>>>(x);

    cudaLaunchAttribute attrs[1];
    attrs[0].id = cudaLaunchAttributeProgrammaticStreamSerialization;
    attrs[0].val.programmaticStreamSerializationAllowed = 1;

    {
        cudaLaunchConfig_t cfg = {};
        cfg.gridDim = dim3(COUT, 1, 1);
        cfg.blockDim = dim3(256, 1, 1);
        cfg.attrs = attrs;
        cfg.numAttrs = 1;
        cudaLaunchKernelEx(&cfg, foldw_kernel, w_proj, gn_scale, gn_bias);
    }
    {
        cudaLaunchConfig_t cfg = {};
        cfg.gridDim = dim3(HW / 64, COUT / 128, 1);
        cfg.blockDim = dim3(256, 1, 1);
        cfg.dynamicSmemBytes = GEMM_SMEM;
        cfg.attrs = attrs;
        cfg.numAttrs = 1;
        cudaLaunchKernelEx(&cfg, gemm_mma_kernel, out);
    }
}

// round 16
// speedup vs baseline: 1.1085x; 1.0145x over previous
#include <cuda_runtime.h>
#include <cuda_fp16.h>
#include <cstdint>

// ---------------- problem constants ----------------
#define HDIM   256
#define WDIM   256
#define HW     16384          // 128*128 output pixels
#define KB     1024           // K (channels)
#define COUT   512
#define NGROUP 128
#define GSIZE  8
#define GN_EPS 1e-5f
#define TITER  16             // 1024 / 64

// ---------------- device scratch ----------------
__device__ __half g_B[(size_t)KB * HW];        // 32 MB: Y fp16, [k][n]
__device__ __half g_A[(size_t)COUT * KB];      // 1 MB: folded W fp16, [o][k]
__device__ float g_psum[2 * KB];               // per-chunk partial sums
__device__ float g_psumsq[2 * KB];
__device__ float g_biaso[COUT];

// ---------------- PTX helpers (target-generic only) ----------------
__device__ __forceinline__ uint32_t s2u(const void* p) {
    uint32_t a;
    asm("{ .reg .u64 t; cvta.to.shared.u64 t, %1; cvt.u32.u64 %0, t; }" : "=r"(a) : "l"(p));
    return a;
}
__device__ __forceinline__ void cp16(uint32_t dst, const void* src) {
    asm volatile("cp.async.cg.shared.global [%0], [%1], 16;" :: "r"(dst), "l"(src));
}
__device__ __forceinline__ void cp_commit() {
    asm volatile("cp.async.commit_group;" ::: "memory");
}
__device__ __forceinline__ void cp_wait1() {
    asm volatile("cp.async.wait_group 1;" ::: "memory");
}
__device__ __forceinline__ void gdc_wait() {
    asm volatile("griddepcontrol.wait;" ::: "memory");
}
__device__ __forceinline__ void ldsm4(uint32_t* r, uint32_t a) {
    asm volatile("ldmatrix.sync.aligned.m8n8.x4.shared.b16 {%0,%1,%2,%3}, [%4];"
                 : "=r"(r[0]), "=r"(r[1]), "=r"(r[2]), "=r"(r[3]) : "r"(a));
}
__device__ __forceinline__ void ldsm4t(uint32_t* r, uint32_t a) {
    asm volatile("ldmatrix.sync.aligned.m8n8.x4.trans.shared.b16 {%0,%1,%2,%3}, [%4];"
                 : "=r"(r[0]), "=r"(r[1]), "=r"(r[2]), "=r"(r[3]) : "r"(a));
}
__device__ __forceinline__ void mma16816(float* d, const uint32_t* a, uint32_t b0, uint32_t b1) {
    asm volatile(
        "mma.sync.aligned.m16n8k16.row.col.f32.f16.f16.f32 "
        "{%0,%1,%2,%3}, {%4,%5,%6,%7}, {%8,%9}, {%0,%1,%2,%3};"
        : "+f"(d[0]), "+f"(d[1]), "+f"(d[2]), "+f"(d[3])
        : "r"(a[0]), "r"(a[1]), "r"(a[2]), "r"(a[3]), "r"(b0), "r"(b1));
}

// ---------------- Kernel A: Haar bands -> fp16 + partial stats (R14-best) -----
// grid (256 channels, 2 half-planes) x 256 threads; 4 iterations/thread.
// Per iteration: 4 consecutive px in quadrant A + 4 in quadrant B
// -> 8 independent float4 loads (8 sectors in flight), 8 x STG.64 stores.
__device__ __forceinline__ void haar4(const float4& r0a, const float4& r0b,
                                      const float4& r1a, const float4& r1b,
                                      float v[4][4]) {
    const float p00[4] = {r0a.x, r0a.z, r0b.x, r0b.z};
    const float p01[4] = {r0a.y, r0a.w, r0b.y, r0b.w};
    const float p10[4] = {r1a.x, r1a.z, r1b.x, r1b.z};
    const float p11[4] = {r1a.y, r1a.w, r1b.y, r1b.w};
    #pragma unroll
    for (int p = 0; p < 4; p++) {
        v[0][p] = 0.5f*( p00[p] + p01[p] + p10[p] + p11[p]);
        v[1][p] = 0.5f*(-p00[p] - p01[p] + p10[p] + p11[p]);
        v[2][p] = 0.5f*(-p00[p] + p01[p] - p10[p] + p11[p]);
        v[3][p] = 0.5f*( p00[p] - p01[p] - p10[p] + p11[p]);
    }
}

__global__ __launch_bounds__(256) void haar_kernel(const float* __restrict__ x) {
    const int cx    = blockIdx.x;            // input channel 0..255
    const int chunk = blockIdx.y;            // 0..1
    const float* xp = x + (size_t)cx * (HDIM * WDIM);

    float s[4] = {0.f, 0.f, 0.f, 0.f};
    float q[4] = {0.f, 0.f, 0.f, 0.f};

    const int base = chunk * 8192;
    for (int t = threadIdx.x * 4; t < 4096; t += 1024) {
        const int iA = base + t;             // quadrant A (4 px)
        const int iB = iA + 4096;            // quadrant B (4 px)
        const int hA = iA >> 7, wA = iA & 127;   // wA multiple of 4
        const int hB = iB >> 7, wB = iB & 127;
        const float* rA0 = xp + (size_t)(2*hA)   * WDIM + 2*wA;
        const float* rA1 = xp + (size_t)(2*hA+1) * WDIM + 2*wA;
        const float* rB0 = xp + (size_t)(2*hB)   * WDIM + 2*wB;
        const float* rB1 = xp + (size_t)(2*hB+1) * WDIM + 2*wB;
        // 8 independent loads issued up front
        const float4 a00 = *(const float4*)(rA0);
        const float4 a01 = *(const float4*)(rA0 + 4);
        const float4 a10 = *(const float4*)(rA1);
        const float4 a11 = *(const float4*)(rA1 + 4);
        const float4 b00 = *(const float4*)(rB0);
        const float4 b01 = *(const float4*)(rB0 + 4);
        const float4 b10 = *(const float4*)(rB1);
        const float4 b11 = *(const float4*)(rB1 + 4);

        float vA[4][4], vB[4][4];            // [band][px]
        haar4(a00, a01, a10, a11, vA);
        haar4(b00, b01, b10, b11, vB);

        #pragma unroll
        for (int b = 0; b < 4; b++) {
            const size_t c = (size_t)b * 256 + cx;
            const __half2 hA01 = __halves2half2(__float2half_rn(vA[b][0]), __float2half_rn(vA[b][1]));
            const __half2 hA23 = __halves2half2(__float2half_rn(vA[b][2]), __float2half_rn(vA[b][3]));
            const __half2 hB01 = __halves2half2(__float2half_rn(vB[b][0]), __float2half_rn(vB[b][1]));
            const __half2 hB23 = __halves2half2(__float2half_rn(vB[b][2]), __float2half_rn(vB[b][3]));
            uint2 stA, stB;
            stA.x = *(const uint32_t*)&hA01; stA.y = *(const uint32_t*)&hA23;
            stB.x = *(const uint32_t*)&hB01; stB.y = *(const uint32_t*)&hB23;
            *(uint2*)&g_B[c * HW + iA] = stA;
            *(uint2*)&g_B[c * HW + iB] = stB;
            #pragma unroll
            for (int p = 0; p < 4; p++) {
                s[b] += vA[b][p] + vB[b][p];
                q[b] += vA[b][p]*vA[b][p] + vB[b][p]*vB[b][p];
            }
        }
    }

    // warp shuffle reduce 8 values, then one smem stage
    float vals[8] = {s[0],s[1],s[2],s[3],q[0],q[1],q[2],q[3]};
    #pragma unroll
    for (int m = 0; m < 8; m++) {
        #pragma unroll
        for (int off = 16; off > 0; off >>= 1)
            vals[m] += __shfl_xor_sync(0xFFFFFFFFu, vals[m], off);
    }
    __shared__ float wred[8][8];             // [warp][metric]
    const int wid = threadIdx.x >> 5;
    const int lid = threadIdx.x & 31;
    if (lid == 0) {
        #pragma unroll
        for (int m = 0; m < 8; m++) wred[wid][m] = vals[m];
    }
    __syncthreads();
    if (threadIdx.x < 8) {
        const int m = threadIdx.x;
        float r = 0.f;
        #pragma unroll
        for (int w = 0; w < 8; w++) r += wred[w][m];
        const int band = m & 3;
        const int idx = chunk * KB + band * 256 + cx;
        if (m < 4) g_psum[idx]   = r;
        else       g_psumsq[idx] = r;
    }
}

// ---------------- Kernel B: stats + fold affine into fp16 weights (PDL) ------
__global__ __launch_bounds__(256) void foldw_kernel(const float* __restrict__ w,
                                                    const float* __restrict__ scale,
                                                    const float* __restrict__ bias) {
    const int tid = threadIdx.x;
    const int o = blockIdx.x;                // 0..511

    // prefetch w BEFORE waiting on haar (overlaps haar tail via PDL)
    float wv[4];
    #pragma unroll
    for (int t = 0; t < 4; t++) wv[t] = w[(size_t)o * KB + tid + t * 256];

    gdc_wait();                              // haar's psum now visible

    __shared__ float sa[KB], sb[KB];
    if (tid < NGROUP) {
        const int g = tid;
        float s = 0.f, q = 0.f;
        #pragma unroll
        for (int j = 0; j < GSIZE; j++) {
            const int c = g*GSIZE + j;
            #pragma unroll
            for (int ch = 0; ch < 2; ch++) {
                s += g_psum[ch * KB + c];
                q += g_psumsq[ch * KB + c];
            }
        }
        const float inv  = 1.0f / (float)(GSIZE * HW);
        const float mean = s * inv;
        const float var  = q * inv - mean * mean;
        const float rstd = rsqrtf(var + GN_EPS);
        #pragma unroll
        for (int j = 0; j < GSIZE; j++) {
            const int c = g*GSIZE + j;
            const float a = scale[c] * rstd;
            sa[c] = a;
            sb[c] = bias[c] - mean * a;
        }
    }
    __syncthreads();

    float part = 0.f;
    #pragma unroll
    for (int t = 0; t < 4; t++) {
        const int c = tid + t * 256;
        g_A[(size_t)o * KB + c] = __float2half_rn(wv[t] * sa[c]);
        part += wv[t] * sb[c];
    }
    __shared__ float red[256];
    red[tid] = part;
    __syncthreads();
    for (int off = 128; off > 0; off >>= 1) {
        if (tid < off) red[tid] += red[tid + off];
        __syncthreads();
    }
    if (tid == 0) g_biaso[o] = red[0];
}

// ---------------- Kernel C: mma.sync fp16 GEMM + bias + ReLU (R9-best, PDL) ----
// CTA tile 128(M) x 64(N), BK=64; 8 warps, warp tile 32x32 (4x2 warp grid).
// Stage: A 16KB + B 8KB = 24KB; 3 stages = 72KB. 3 CTAs/SM (24 warps).
#define STAGE_BYTES 24576
#define GEMM_SMEM   (3 * STAGE_BYTES)

__device__ __forceinline__ void load_stage(int tid, int j, uint32_t sbase, int m0, int n0) {
    const uint32_t st = sbase + (uint32_t)(j % 3) * STAGE_BYTES;
    const int koff = j << 6;                 // 0..960
    const __half* Ab = g_A + (size_t)m0 * KB + koff;
    const __half* Bb = g_B + (size_t)koff * HW + n0;
    // A: 128 rows(m) x 8 chunks(kc of 8 halves); unit = m*8 + (kc ^ (m&7))
    #pragma unroll
    for (int t = 0; t < 4; t++) {
        const int u = tid + t * 256;
        const int m = u >> 3, kc = u & 7;
        const uint32_t du = (uint32_t)(m * 8 + (kc ^ (m & 7))) * 16;
        cp16(st + du, Ab + (size_t)m * KB + kc * 8);
    }
    // B: 64 rows(k) x 8 chunks(nc of 8 halves); unit = k*8 + (nc ^ (k&7))
    #pragma unroll
    for (int t = 0; t < 2; t++) {
        const int u = tid + t * 256;
        const int k = u >> 3, nc = u & 7;
        const uint32_t du = (uint32_t)(k * 8 + (nc ^ (k & 7)));
        cp16(st + 16384 + du * 16, Bb + (size_t)k * HW + nc * 8);
    }
}

__global__ __launch_bounds__(256, 3) void gemm_mma_kernel(float* __restrict__ out) {
    extern __shared__ char smem[];
    const uint32_t sbase = s2u(smem);
    const int tid  = threadIdx.x;
    const int wid  = tid >> 5;
    const int lane = tid & 31;
    const int n0 = blockIdx.x * 64;
    const int m0 = blockIdx.y * 128;
    const int wm = wid >> 1;                 // 0..3
    const int wn = wid & 1;                  // 0..1
    const int mbase = wm * 32;
    const int nbase = wn * 32;

    const int r15 = lane & 15;
    const int hi  = lane >> 4;
    const int s7  = r15 & 7;

    float acc[2][4][4];
    #pragma unroll
    for (int i = 0; i < 2; i++)
        #pragma unroll
        for (int j = 0; j < 4; j++)
            #pragma unroll
            for (int q = 0; q < 4; q++) acc[i][j][q] = 0.f;

    gdc_wait();                              // foldw (and transitively haar) done

    load_stage(tid, 0, sbase, m0, n0); cp_commit();
    load_stage(tid, 1, sbase, m0, n0); cp_commit();

    for (int j = 0; j < TITER; j++) {
        cp_wait1();
        __syncthreads();
        if (j + 2 < TITER) load_stage(tid, j + 2, sbase, m0, n0);
        cp_commit();

        const uint32_t st = sbase + (uint32_t)(j % 3) * STAGE_BYTES;
        #pragma unroll
        for (int kk = 0; kk < 4; kk++) {
            uint32_t b[2][4];
            #pragma unroll
            for (int p = 0; p < 2; p++) {
                const int k   = kk * 16 + r15;
                const int ncg = wn * 4 + p * 2 + hi;
                ldsm4t(b[p], st + 16384 + (uint32_t)((k * 8 + (ncg ^ s7)) * 16));
            }
            uint32_t a[2][4];
            #pragma unroll
            for (int mf = 0; mf < 2; mf++) {
                const int row = mbase + mf * 16 + r15;
                ldsm4(a[mf], st + (uint32_t)(row * 128) + (uint32_t)(((kk * 2 + hi) ^ s7) * 16));
            }
            #pragma unroll
            for (int mf = 0; mf < 2; mf++)
                #pragma unroll
                for (int nf = 0; nf < 4; nf++)
                    mma16816(acc[mf][nf], a[mf], b[nf >> 1][(nf & 1) * 2],
                             b[nf >> 1][(nf & 1) * 2 + 1]);
        }
    }

    // epilogue: bias + ReLU + float2 stores
    const int qrow = lane >> 2;
    const int qcol = (lane & 3) * 2;
    #pragma unroll
    for (int mf = 0; mf < 2; mf++) {
        const int row0 = m0 + mbase + mf * 16 + qrow;
        const float bi0 = g_biaso[row0];
        const float bi1 = g_biaso[row0 + 8];
        float* o0 = out + (size_t)row0 * HW + n0 + nbase + qcol;
        float* o1 = out + (size_t)(row0 + 8) * HW + n0 + nbase + qcol;
        #pragma unroll
        for (int nf = 0; nf < 4; nf++) {
            float2 v0, v1;
            v0.x = fmaxf(acc[mf][nf][0] + bi0, 0.f);
            v0.y = fmaxf(acc[mf][nf][1] + bi0, 0.f);
            v1.x = fmaxf(acc[mf][nf][2] + bi1, 0.f);
            v1.y = fmaxf(acc[mf][nf][3] + bi1, 0.f);
            *(float2*)(o0 + nf * 8) = v0;
            *(float2*)(o1 + nf * 8) = v1;
        }
    }
}

// ---------------- launch ----------------
extern "C" void kernel_launch(void* const* d_in, const int* in_sizes, int n_in,
                              void* d_out, int out_size) {
    const float* x        = (const float*)d_in[0];
    const float* gn_scale = (const float*)d_in[1];
    const float* gn_bias  = (const float*)d_in[2];
    const float* w_proj   = (const float*)d_in[3];
    float* out = (float*)d_out;

    cudaFuncSetAttribute(gemm_mma_kernel,
                         cudaFuncAttributeMaxDynamicSharedMemorySize, GEMM_SMEM);

    dim3 hgrid(256, 2);
    haar_kernel<<<hgrid, 256>>>(x);

    cudaLaunchAttribute attrs[1];
    attrs[0].id = cudaLaunchAttributeProgrammaticStreamSerialization;
    attrs[0].val.programmaticStreamSerializationAllowed = 1;

    {
        cudaLaunchConfig_t cfg = {};
        cfg.gridDim = dim3(COUT, 1, 1);
        cfg.blockDim = dim3(256, 1, 1);
        cfg.attrs = attrs;
        cfg.numAttrs = 1;
        cudaLaunchKernelEx(&cfg, foldw_kernel, w_proj, gn_scale, gn_bias);
    }
    {
        cudaLaunchConfig_t cfg = {};
        cfg.gridDim = dim3(HW / 64, COUT / 128, 1);
        cfg.blockDim = dim3(256, 1, 1);
        cfg.dynamicSmemBytes = GEMM_SMEM;
        cfg.attrs = attrs;
        cfg.numAttrs = 1;
        cudaLaunchKernelEx(&cfg, gemm_mma_kernel, out);
    }
}